// round 6
// baseline (speedup 1.0000x reference)
#include <cuda_runtime.h>

// Problem constants
#define NB 16
#define NT 256
#define NK 128
#define ND 256   // D_E == D_K == 256
#define NU 128

// Scratch (allocation-free rule: __device__ globals)
__device__ float g_e[NB * NT * NU];     // [b*NT + t][u]   (e-proj + b1)
__device__ float g_kpT[NB * NU * NK];   // [b][u][k]       (k-proj + b2, transposed)

__device__ __forceinline__ float tanh_fast(float x) {
    float y;
    asm("tanh.approx.f32 %0, %1;" : "=f"(y) : "f"(x));
    return y;
}

// ---------------------------------------------------------------------------
// Projection kernel: blocks [0,256) do e = enc @ W1 + b1  (4096 rows)
//                    blocks [256,384) do kp = knw @ W2 + b2 (2048 rows, stored transposed)
// 16 rows x 128 cols per block, k-chunks of 32. 256 threads.
// ---------------------------------------------------------------------------
__global__ __launch_bounds__(256) void proj_kernel(
    const float* __restrict__ enc, const float* __restrict__ knw,
    const float* __restrict__ W1, const float* __restrict__ b1,
    const float* __restrict__ W2, const float* __restrict__ b2)
{
    const int blk = blockIdx.x;
    const bool isE = (blk < 256);
    const float* __restrict__ A    = isE ? enc : knw;
    const float* __restrict__ W    = isE ? W1  : W2;
    const float* __restrict__ bias = isE ? b1  : b2;
    const int row0 = (isE ? blk : (blk - 256)) * 16;

    __shared__ float As[16][32];
    __shared__ float Bs[32][128];

    const int tid = threadIdx.x;
    const int tx  = tid & 31;   // lane -> 4 output cols
    const int ty  = tid >> 5;   // warp -> 2 output rows

    float4 acc0 = make_float4(0.f, 0.f, 0.f, 0.f);
    float4 acc1 = make_float4(0.f, 0.f, 0.f, 0.f);

    for (int kc = 0; kc < ND; kc += 32) {
        // A tile: 16 x 32 floats = 128 float4 (first 128 threads)
        if (tid < 128) {
            int r  = tid >> 3;   // 0..15
            int c4 = tid & 7;    // 0..7
            float4 a = *(const float4*)&A[(row0 + r) * ND + kc + c4 * 4];
            *(float4*)&As[r][c4 * 4] = a;
        }
        // B tile: 32 x 128 floats = 1024 float4, 4 per thread
        #pragma unroll
        for (int i = 0; i < 4; i++) {
            int lin = tid + i * 256;    // 0..1023
            int r   = lin >> 5;         // 0..31
            int c4  = lin & 31;         // 0..31
            *(float4*)&Bs[r][c4 * 4] = *(const float4*)&W[(kc + r) * NU + c4 * 4];
        }
        __syncthreads();

        #pragma unroll
        for (int kk = 0; kk < 32; kk++) {
            float4 bv = *(float4*)&Bs[kk][tx * 4];
            float a0 = As[ty * 2 + 0][kk];
            float a1 = As[ty * 2 + 1][kk];
            acc0.x += a0 * bv.x; acc0.y += a0 * bv.y;
            acc0.z += a0 * bv.z; acc0.w += a0 * bv.w;
            acc1.x += a1 * bv.x; acc1.y += a1 * bv.y;
            acc1.z += a1 * bv.z; acc1.w += a1 * bv.w;
        }
        __syncthreads();
    }

    float4 bb = *(const float4*)&bias[tx * 4];
    acc0.x += bb.x; acc0.y += bb.y; acc0.z += bb.z; acc0.w += bb.w;
    acc1.x += bb.x; acc1.y += bb.y; acc1.z += bb.z; acc1.w += bb.w;

    const int r0 = row0 + ty * 2;
    if (isE) {
        *(float4*)&g_e[(r0 + 0) * NU + tx * 4] = acc0;
        *(float4*)&g_e[(r0 + 1) * NU + tx * 4] = acc1;
    } else {
        // transpose on store: g_kpT[b][u][k]
        int b0 = r0 >> 7;
        int k0 = r0 & 127;
        float* dst = &g_kpT[b0 * NU * NK];
        dst[(4 * tx + 0) * NK + k0] = acc0.x;
        dst[(4 * tx + 1) * NK + k0] = acc0.y;
        dst[(4 * tx + 2) * NK + k0] = acc0.z;
        dst[(4 * tx + 3) * NK + k0] = acc0.w;
        dst[(4 * tx + 0) * NK + k0 + 1] = acc1.x;
        dst[(4 * tx + 1) * NK + k0 + 1] = acc1.y;
        dst[(4 * tx + 2) * NK + k0 + 1] = acc1.z;
        dst[(4 * tx + 3) * NK + k0 + 1] = acc1.w;
    }
}

// ---------------------------------------------------------------------------
// Fused score + softmax + context kernel.
// Grid: (NT/32, NB). Block: 256 threads (8 warps), each warp owns 4 t's.
// Dynamic smem: know[128][256] + kpT[128][128] + e/attn[32][128] + V[128]
//             = (32768 + 16384 + 4096 + 128) * 4 = 213504 bytes.
// ---------------------------------------------------------------------------
__global__ __launch_bounds__(256) void fused_kernel(
    const float* __restrict__ knw, const float* __restrict__ V,
    float* __restrict__ out)
{
    extern __shared__ float smem[];
    float* know_s = smem;                       // [k][d]  32768
    float* kpT_s  = know_s + NK * ND;           // [u][k]  16384
    float* e_s    = kpT_s + NU * NK;            // [tl][u] 4096 (reused as attn [tl][k])
    float* v_s    = e_s + 32 * NU;              // 128

    const int b    = blockIdx.y;
    const int t0   = blockIdx.x * 32;
    const int tid  = threadIdx.x;
    const int lane = tid & 31;
    const int w    = tid >> 5;

    // cooperative stage (all float4, coalesced)
    {
        const float4* src = (const float4*)(knw + b * NK * ND);
        float4* dst = (float4*)know_s;
        #pragma unroll
        for (int i = 0; i < (NK * ND / 4) / 256; i++)
            dst[tid + i * 256] = src[tid + i * 256];
    }
    {
        const float4* src = (const float4*)(g_kpT + b * NU * NK);
        float4* dst = (float4*)kpT_s;
        #pragma unroll
        for (int i = 0; i < (NU * NK / 4) / 256; i++)
            dst[tid + i * 256] = src[tid + i * 256];
    }
    {
        const float4* src = (const float4*)(g_e + (b * NT + t0) * NU);
        float4* dst = (float4*)e_s;
        #pragma unroll
        for (int i = 0; i < (32 * NU / 4) / 256; i++)
            dst[tid + i * 256] = src[tid + i * 256];
    }
    if (tid < NU) v_s[tid] = V[tid];
    __syncthreads();

    const int tl = 4 * w;   // first local t this warp owns

    // ---- score: acc[tt].{x,y,z,w} = score(t=tl+tt, k=4*lane+{0..3}) ----
    float4 acc[4];
    #pragma unroll
    for (int tt = 0; tt < 4; tt++) acc[tt] = make_float4(0.f, 0.f, 0.f, 0.f);

    #pragma unroll 4
    for (int u = 0; u < NU; u++) {
        float4 kp = ((const float4*)&kpT_s[u * NK])[lane];
        float vu = v_s[u];
        #pragma unroll
        for (int tt = 0; tt < 4; tt++) {
            float ev = e_s[(tl + tt) * NU + u];
            acc[tt].x += vu * tanh_fast(ev + kp.x);
            acc[tt].y += vu * tanh_fast(ev + kp.y);
            acc[tt].z += vu * tanh_fast(ev + kp.z);
            acc[tt].w += vu * tanh_fast(ev + kp.w);
        }
    }

    // ---- softmax over K (per t, within warp); bV cancels in softmax ----
    #pragma unroll
    for (int tt = 0; tt < 4; tt++) {
        float4 s = acc[tt];
        float m = fmaxf(fmaxf(s.x, s.y), fmaxf(s.z, s.w));
        #pragma unroll
        for (int o = 16; o > 0; o >>= 1)
            m = fmaxf(m, __shfl_xor_sync(0xffffffffu, m, o));
        float4 p;
        p.x = __expf(s.x - m);
        p.y = __expf(s.y - m);
        p.z = __expf(s.z - m);
        p.w = __expf(s.w - m);
        float sum = (p.x + p.y) + (p.z + p.w);
        #pragma unroll
        for (int o = 16; o > 0; o >>= 1)
            sum += __shfl_xor_sync(0xffffffffu, sum, o);
        float inv = __fdividef(1.0f, sum);
        p.x *= inv; p.y *= inv; p.z *= inv; p.w *= inv;
        // overwrite this warp's own e row with attn (only this warp reads it)
        ((float4*)&e_s[(tl + tt) * NU])[lane] = p;
    }
    __syncwarp();

    // ---- context: out[t][d] = sum_k attn[t][k] * know[k][d] ----
    // lane covers d = 4*lane..+3 and 128+4*lane..+3
    float4 c0[4], c1[4];
    #pragma unroll
    for (int tt = 0; tt < 4; tt++) {
        c0[tt] = make_float4(0.f, 0.f, 0.f, 0.f);
        c1[tt] = make_float4(0.f, 0.f, 0.f, 0.f);
    }
    #pragma unroll 2
    for (int k = 0; k < NK; k++) {
        float4 lo = ((const float4*)&know_s[k * ND])[lane];
        float4 hi = ((const float4*)&know_s[k * ND])[lane + 32];
        #pragma unroll
        for (int tt = 0; tt < 4; tt++) {
            float a = e_s[(tl + tt) * NU + k];
            c0[tt].x += a * lo.x; c0[tt].y += a * lo.y;
            c0[tt].z += a * lo.z; c0[tt].w += a * lo.w;
            c1[tt].x += a * hi.x; c1[tt].y += a * hi.y;
            c1[tt].z += a * hi.z; c1[tt].w += a * hi.w;
        }
    }

    #pragma unroll
    for (int tt = 0; tt < 4; tt++) {
        int t = t0 + tl + tt;
        float4* o4 = (float4*)(out + (b * NT + t) * ND);
        o4[lane]      = c0[tt];
        o4[lane + 32] = c1[tt];
    }
}

// ---------------------------------------------------------------------------
// Launch
// ---------------------------------------------------------------------------
extern "C" void kernel_launch(void* const* d_in, const int* in_sizes, int n_in,
                              void* d_out, int out_size)
{
    const float* knw = (const float*)d_in[0];   // knowledge_onehot [16,128,256]
    const float* enc = (const float*)d_in[1];   // encoder_outputs  [16,256,256]
    const float* W1  = (const float*)d_in[2];
    const float* b1  = (const float*)d_in[3];
    const float* W2  = (const float*)d_in[4];
    const float* b2  = (const float*)d_in[5];
    const float* V   = (const float*)d_in[6];
    // d_in[7] = bV: shifts all scores equally -> cancels in softmax. Unused.

    // Defensive: distinguish the two activation tensors by element count.
    if (n_in >= 2 && in_sizes[0] == NB * NT * ND && in_sizes[1] == NB * NK * ND) {
        const float* tmp = knw; knw = enc; enc = tmp;
    }

    const int smem_bytes = (NK * ND + NU * NK + 32 * NU + NU) * (int)sizeof(float); // 213504
    cudaFuncSetAttribute(fused_kernel, cudaFuncAttributeMaxDynamicSharedMemorySize,
                         smem_bytes);

    proj_kernel<<<384, 256>>>(enc, knw, W1, b1, W2, b2);

    dim3 grid(NT / 32, NB);
    fused_kernel<<<grid, 256, smem_bytes>>>(knw, V, (float*)d_out);

    (void)n_in; (void)out_size;
}